// round 15
// baseline (speedup 1.0000x reference)
#include <cuda_runtime.h>
#include <cuda_bf16.h>
#include <math_constants.h>

// Problem constants (fixed by the benchmark)
#define BB 2
#define LL 2048
#define HH 8
#define DD 64
#define UU 80
#define SS 80
#define BHN (BB*HH)
#define SPLIT 16
#define CHUNK (LL/SPLIT)      // 128 keys per split block
#define UST 4                 // u-stride for winner loop (~4 winners typical)
#define NTB 16                // presort buckets (j>>7 -> 32KB key tiles)

// Scratch (device globals; zero-initialized at module load)
__device__ unsigned short g_sidx[LL*SS];  // tile-sorted sample indices (per l)
__device__ float g_M[BB*HH*LL];           // sparsity measure M[b,h,l]
__device__ float g_vmean[BHN*DD];         // V column sums (atomic; reset by k_topk)
__device__ int   g_cu[BHN*UU];            // per-(bh,u) split counter (self-reset)
__device__ int   g_nw[BHN];               // winners per (b,h)
__device__ int   g_wl[BHN*UU];            // winner: source token l
__device__ int   g_wj[BHN*UU];            // winner: output slot j
__device__ float g_pmax[BHN*UU*SPLIT];    // split-softmax partial max
__device__ float g_psum[BHN*UU*SPLIT];    // split-softmax partial sum(exp)
__device__ float g_pv  [BHN*UU*SPLIT*DD]; // split partial (unnormalized) PV

// ---------------------------------------------------------------------------
// Kernel 0: presort each l-row's 80 sample indices by 32KB key tile (j>>7)
// into a global u16 table. One thread per l; pure ALU/local work (no smem
// atomics -> nothing on the hot kernel's L1TEX pipe). Order within a bucket
// keeps original s order (sum order shifts ~1ulp; max is exact).
// ---------------------------------------------------------------------------
__global__ void k_presort(const int* __restrict__ idx) {
    int l = blockIdx.x * 256 + threadIdx.x;
    if (l >= LL) return;
    const int4* ir = (const int4*)(idx + (size_t)l*SS);
    int c[NTB];
    #pragma unroll
    for (int i = 0; i < NTB; ++i) c[i] = 0;
    #pragma unroll 5
    for (int q4 = 0; q4 < SS/4; ++q4) {
        int4 v = ir[q4];
        c[v.x >> 7]++; c[v.y >> 7]++; c[v.z >> 7]++; c[v.w >> 7]++;
    }
    int cur[NTB]; int run = 0;
    #pragma unroll
    for (int i = 0; i < NTB; ++i) { cur[i] = run; run += c[i]; }
    unsigned short* orow = g_sidx + (size_t)l*SS;
    #pragma unroll 5
    for (int q4 = 0; q4 < SS/4; ++q4) {
        int4 v = ir[q4];
        orow[cur[v.x >> 7]++] = (unsigned short)v.x;
        orow[cur[v.y >> 7]++] = (unsigned short)v.y;
        orow[cur[v.z >> 7]++] = (unsigned short)v.z;
        orow[cur[v.w >> 7]++] = (unsigned short)v.w;
    }
}

// ---------------------------------------------------------------------------
// Kernel 1: sampled scores -> M[b,h,l] + V column sums. R5-validated gather
// shape (warp per (b,h,l); 4 independent 256B LDG gathers per warp-iter),
// indices read PRESORTED by key tile so co-resident same-bh CTAs walk tiles
// in the same order (L1 hot set). ~2KB smem, no smem atomics -> L1TEX pipe
// carries only the gather.
// ---------------------------------------------------------------------------
__global__ void k_sample(const float* __restrict__ Q, const float* __restrict__ K,
                         const float* __restrict__ V) {
    __shared__ float sv[8][64];

    int t = threadIdx.x, lane = t & 31, warp = t >> 5;
    int gw = blockIdx.x * 8 + warp;
    int l  = gw & (LL-1);
    int bh = gw >> 11;
    int b = bh >> 3, h = bh & 7;
    int grp = lane >> 3, lg = lane & 7;

    const float* qrow = Q + (((size_t)b*LL + l)*HH + h)*DD;
    float4 q0 = *(const float4*)(qrow + lg*8);
    float4 q1 = *(const float4*)(qrow + lg*8 + 4);

    // V row for this l (coalesced float2 per lane)
    float2 vv = *(const float2*)(V + (((size_t)b*LL + l)*HH + h)*DD + lane*2);
    sv[warp][lane*2] = vv.x; sv[warp][lane*2+1] = vv.y;

    const unsigned short* irow = g_sidx + (size_t)l*SS;
    float vmax = -CUDART_INF_F, vsum = 0.f;

    #pragma unroll 5
    for (int it = 0; it < SS/4; ++it) {
        int j = irow[it*4 + grp];
        const float* krow = K + (((size_t)b*LL + j)*HH + h)*DD + lg*8;
        float4 k0 = *(const float4*)(krow);
        float4 k1 = *(const float4*)(krow + 4);
        float p = q0.x*k0.x + q0.y*k0.y + q0.z*k0.z + q0.w*k0.w
                + q1.x*k1.x + q1.y*k1.y + q1.z*k1.z + q1.w*k1.w;
        p += __shfl_xor_sync(0xffffffffu, p, 4);
        p += __shfl_xor_sync(0xffffffffu, p, 2);
        p += __shfl_xor_sync(0xffffffffu, p, 1);
        vmax = fmaxf(vmax, p);
        vsum += p;
    }
    vmax = fmaxf(vmax, __shfl_xor_sync(0xffffffffu, vmax, 8));
    vmax = fmaxf(vmax, __shfl_xor_sync(0xffffffffu, vmax, 16));
    vsum += __shfl_xor_sync(0xffffffffu, vsum, 8);
    vsum += __shfl_xor_sync(0xffffffffu, vsum, 16);
    if (lane == 0) g_M[gw] = vmax - vsum * (1.0f/(float)LL);

    __syncthreads();
    if (t < 64) {
        float s = sv[0][t] + sv[1][t] + sv[2][t] + sv[3][t]
                + sv[4][t] + sv[5][t] + sv[6][t] + sv[7][t];
        atomicAdd(&g_vmean[bh*64 + t], s);
    }
}

// ---------------------------------------------------------------------------
// Kernel 2: per-(b,h) top-80 (radix select + bitonic, exact jax.lax.top_k
// semantics), winner replay, V_mean broadcast fill. (R13/R14-validated body.)
// ---------------------------------------------------------------------------
__global__ void k_topk(float* __restrict__ out) {
    int bh = blockIdx.x, t = threadIdx.x, lane = t & 31;
    int b = bh >> 3, h = bh & 7;
    __shared__ unsigned su[LL];
    __shared__ int hist[256];
    __shared__ int scnt[2];
    __shared__ unsigned long long keys[128];
    __shared__ int eqbuf[256];
    __shared__ int cgt, ceq;
    __shared__ int stop[UU];
    __shared__ int win[UU];
    __shared__ float mean[64];

    if (t < 64) {
        mean[t] = g_vmean[bh*64 + t] * (1.0f/(float)LL);
        g_vmean[bh*64 + t] = 0.f;           // reset for next graph replay
    }
    for (int i = t; i < LL; i += 256) {
        unsigned bb = __float_as_uint(g_M[bh*LL + i]);
        su[i] = (bb & 0x80000000u) ? ~bb : (bb | 0x80000000u);
    }
    __syncthreads();

    // broadcast-fill all 80 output rows with V_mean (winners overwritten later)
    for (int e = t; e < UU*64; e += 256) {
        int j = e >> 6, d = e & 63;
        out[(((size_t)b*UU + j)*HH + h)*DD + d] = mean[d];
    }

    // 4-pass byte radix: T = 80th-largest transformed value
    unsigned prefix = 0, prefmask = 0;
    int need = UU;
    for (int pass = 0; pass < 4; ++pass) {
        int shift = 24 - pass*8;
        hist[t] = 0;
        __syncthreads();
        for (int i = t; i < LL; i += 256) {
            unsigned u = su[i];
            if ((u & prefmask) == prefix) atomicAdd(&hist[(u >> shift) & 0xFF], 1);
        }
        __syncthreads();
        if (t < 32) {
            int base = 255 - t*8;
            int s = 0;
            #pragma unroll
            for (int e = 0; e < 8; ++e) s += hist[base - e];
            int pre = s;
            #pragma unroll
            for (int o = 1; o < 32; o <<= 1) {
                int v = __shfl_up_sync(0xffffffffu, pre, o);
                if (lane >= o) pre += v;
            }
            int excl = pre - s;
            if (excl < need && need <= pre) {
                int acc = excl;
                #pragma unroll
                for (int e = 0; e < 8; ++e) {
                    int hb = hist[base - e];
                    if (acc + hb >= need) { scnt[0] = base - e; scnt[1] = acc; break; }
                    acc += hb;
                }
            }
        }
        __syncthreads();
        prefix |= ((unsigned)scnt[0]) << shift;
        prefmask |= 0xFFu << shift;
        need -= scnt[1];
        __syncthreads();
    }
    unsigned T = prefix;

    if (t == 0) { cgt = 0; ceq = 0; }
    __syncthreads();
    for (int i = t; i < LL; i += 256) {
        unsigned u = su[i];
        if (u > T) {
            int p = atomicAdd(&cgt, 1);
            keys[p] = ((unsigned long long)u << 32) | (unsigned)(~i);
        } else if (u == T) {
            int p = atomicAdd(&ceq, 1);
            if (p < 256) eqbuf[p] = i;
        }
    }
    __syncthreads();
    if (t == 0) {
        int base = cgt;
        int ce = min(ceq, 256);
        for (int k = 0; k < need; ++k) {
            int mi = 0x7fffffff, mp = -1;
            for (int e = 0; e < ce; ++e)
                if (eqbuf[e] < mi) { mi = eqbuf[e]; mp = e; }
            keys[base + k] = ((unsigned long long)T << 32) | (unsigned)(~mi);
            eqbuf[mp] = 0x7fffffff;
        }
    }
    for (int i = t; i < 128; i += 256) if (i >= UU) keys[i] = 0ULL;
    __syncthreads();

    // bitonic sort, 128 elements, descending (=> value desc, index asc)
    for (int ksz = 2; ksz <= 128; ksz <<= 1) {
        for (int jst = ksz >> 1; jst > 0; jst >>= 1) {
            __syncthreads();
            if (t < 128) {
                int ixj = t ^ jst;
                if (ixj > t) {
                    unsigned long long a = keys[t], c = keys[ixj];
                    bool up = (t & ksz) == 0;
                    if (up ? (a < c) : (a > c)) { keys[t] = c; keys[ixj] = a; }
                }
            }
        }
    }
    __syncthreads();

    if (t < UU) {
        stop[t] = (int)(~(unsigned)(keys[t] & 0xffffffffu));
        win[t] = -1;
    }
    __syncthreads();
    if (t == 0) {
        for (int u = 0; u < UU; ++u) { int jj = min(stop[u], UU-1); win[jj] = u; }
        int n = 0;
        for (int jj = 0; jj < UU; ++jj) {
            if (win[jj] >= 0) {
                g_wl[bh*UU + n] = stop[win[jj]];
                g_wj[bh*UU + n] = jj;
                n++;
            }
        }
        g_nw[bh] = n;
    }
}

// ---------------------------------------------------------------------------
// Kernel 3: split-K attention partials for winner rows with last-split-block
// combine. SPLIT=16, CHUNK=128, 256 threads, grid (bh, UST=4, SPLIT).
// (Body measured 18.8-19.5us across R6-R14 — verbatim; grid y shrunk to the
// typical winner count, loop covers any overflow.)
// ---------------------------------------------------------------------------
__global__ void k_attn(const float* __restrict__ Q, const float* __restrict__ K,
                       const float* __restrict__ V, float* __restrict__ out) {
    int bh = blockIdx.x;
    int n = g_nw[bh];
    int b = bh >> 3, h = bh & 7;
    int sp = blockIdx.z, k0 = sp * CHUNK;

    __shared__ float q[DD];
    __shared__ float p[CHUNK];
    __shared__ float red[8];
    __shared__ float ac[4][64];
    __shared__ int lastf;
    int t = threadIdx.x, lane = t & 31, warp = t >> 5;
    int grp = lane >> 3, lg = lane & 7;

    for (int u = blockIdx.y; u < n; u += UST) {
        int l = g_wl[bh*UU + u];
        if (t < DD) q[t] = Q[(((size_t)b*LL + l)*HH + h)*DD + t];
        __syncthreads();
        float4 q0 = ((float4*)q)[lg*2];
        float4 q1 = ((float4*)q)[lg*2 + 1];

        float lmax = -CUDART_INF_F;
        #pragma unroll
        for (int it = 0; it < 4; ++it) {
            int kk = warp*16 + it*4 + grp;
            const float* kr = K + (((size_t)b*LL + k0 + kk)*HH + h)*DD + lg*8;
            float4 k0v = *(const float4*)kr;
            float4 k1v = *(const float4*)(kr + 4);
            float s = q0.x*k0v.x + q0.y*k0v.y + q0.z*k0v.z + q0.w*k0v.w
                    + q1.x*k1v.x + q1.y*k1v.y + q1.z*k1v.z + q1.w*k1v.w;
            s += __shfl_xor_sync(0xffffffffu, s, 4);
            s += __shfl_xor_sync(0xffffffffu, s, 2);
            s += __shfl_xor_sync(0xffffffffu, s, 1);
            s *= 0.125f;                 // 1/sqrt(64)
            if (lg == 0) p[kk] = s;
            lmax = fmaxf(lmax, s);
        }
        lmax = fmaxf(lmax, __shfl_xor_sync(0xffffffffu, lmax, 8));
        lmax = fmaxf(lmax, __shfl_xor_sync(0xffffffffu, lmax, 16));
        if (lane == 0) red[warp] = lmax;
        __syncthreads();
        if (t == 0) { float m = red[0]; for (int w = 1; w < 8; ++w) m = fmaxf(m, red[w]); red[0] = m; }
        __syncthreads();
        float m = red[0];
        __syncthreads();

        float e = 0.f;
        if (t < CHUNK) { e = __expf(p[t] - m); p[t] = e; }
        float ls = e;
        #pragma unroll
        for (int o = 16; o; o >>= 1) ls += __shfl_xor_sync(0xffffffffu, ls, o);
        if (lane == 0) red[warp] = ls;
        __syncthreads();
        float ssumv = red[0]+red[1]+red[2]+red[3]+red[4]+red[5]+red[6]+red[7];

        int g4 = t >> 6, d = t & 63;
        float acc = 0.f;
        #pragma unroll 8
        for (int kk = g4; kk < CHUNK; kk += 4)
            acc += p[kk] * V[(((size_t)b*LL + k0 + kk)*HH + h)*DD + d];
        ac[g4][d] = acc;
        __syncthreads();
        int base = (bh*UU + u)*SPLIT + sp;
        if (t < 64)
            g_pv[(size_t)base*DD + t] = ac[0][t] + ac[1][t] + ac[2][t] + ac[3][t];
        if (t == 0) { g_pmax[base] = m; g_psum[base] = ssumv; }

        __threadfence();
        __syncthreads();
        if (t == 0) {
            int old = atomicAdd(&g_cu[bh*UU + u], 1);
            lastf = (old == SPLIT - 1);
        }
        __syncthreads();
        if (lastf) {
            if (t == 0) g_cu[bh*UU + u] = 0;   // self-reset for replay
            if (t < 64) {
                int cb = (bh*UU + u)*SPLIT;
                float mm = -CUDART_INF_F;
                #pragma unroll
                for (int i = 0; i < SPLIT; ++i) mm = fmaxf(mm, g_pmax[cb + i]);
                float s = 0.f, pv = 0.f;
                #pragma unroll
                for (int i = 0; i < SPLIT; ++i) {
                    float w = __expf(g_pmax[cb + i] - mm);
                    s  += g_psum[cb + i] * w;
                    pv += g_pv[(size_t)(cb + i)*DD + t] * w;
                }
                int j = g_wj[bh*UU + u];
                out[(((size_t)b*UU + j)*HH + h)*DD + t] = pv / s;
            }
        }
        __syncthreads();
    }
}

// ---------------------------------------------------------------------------
extern "C" void kernel_launch(void* const* d_in, const int* in_sizes, int n_in,
                              void* d_out, int out_size) {
    const float* Q   = (const float*)d_in[0];
    const float* K   = (const float*)d_in[1];
    const float* V   = (const float*)d_in[2];
    const int*   idx = (const int*)d_in[3];
    float* out = (float*)d_out;

    k_presort<<<LL/256, 256>>>(idx);
    k_sample<<<(BB*HH*LL)/8, 256>>>(Q, K, V);
    k_topk<<<BHN, 256>>>(out);
    dim3 ga(BHN, UST, SPLIT);
    k_attn<<<ga, 256>>>(Q, K, V, out);
}

// round 16
// speedup vs baseline: 1.0711x; 1.0711x over previous
#include <cuda_runtime.h>
#include <cuda_bf16.h>
#include <math_constants.h>

// Problem constants (fixed by the benchmark)
#define BB 2
#define LL 2048
#define HH 8
#define DD 64
#define UU 80
#define SS 80
#define BHN (BB*HH)
#define SPLIT 16
#define CHUNK (LL/SPLIT)      // 128 keys per split block
#define UST 8                 // u-stride for winner loop (measured-good)
#define NTB 16                // presort buckets (j>>7 -> 32KB key tiles)
#define PSL 64                // presort rows per block
#define PSROW 82              // smem row stride in u16 (41 words, coprime w/ 32 banks)

// Scratch (device globals; zero-initialized at module load)
__device__ unsigned short g_sidx[LL*SS];  // tile-sorted sample indices (per l)
__device__ float g_M[BB*HH*LL];           // sparsity measure M[b,h,l]
__device__ float g_vmean[BHN*DD];         // V column sums (atomic; reset by k_topk)
__device__ int   g_cu[BHN*UU];            // per-(bh,u) split counter (self-reset)
__device__ int   g_nw[BHN];               // winners per (b,h)
__device__ int   g_wl[BHN*UU];            // winner: source token l
__device__ int   g_wj[BHN*UU];            // winner: output slot j
__device__ float g_pmax[BHN*UU*SPLIT];    // split-softmax partial max
__device__ float g_psum[BHN*UU*SPLIT];    // split-softmax partial sum(exp)
__device__ float g_pv  [BHN*UU*SPLIT*DD]; // split partial (unnormalized) PV

// ---------------------------------------------------------------------------
// Kernel 0 (v2): presort each l-row's 80 sample indices by 32KB key tile
// (j>>7) into g_sidx. Scatter goes to SMEM (bank-spread row stride), then a
// block-coalesced u32 copy writes the result — fixes R15's scattered-STG.U16
// disaster (50us -> ~3us). 32 blocks x 64 threads, one thread per l.
// ---------------------------------------------------------------------------
__global__ void k_presort(const int* __restrict__ idx) {
    __shared__ unsigned short srow[PSL*PSROW];   // 10.5KB
    int t = threadIdx.x;                         // 64 threads
    int l0 = blockIdx.x * PSL;
    int l = l0 + t;

    const int4* ir = (const int4*)(idx + (size_t)l*SS);
    int c[NTB];
    #pragma unroll
    for (int i = 0; i < NTB; ++i) c[i] = 0;
    #pragma unroll 5
    for (int q4 = 0; q4 < SS/4; ++q4) {
        int4 v = ir[q4];
        c[v.x >> 7]++; c[v.y >> 7]++; c[v.z >> 7]++; c[v.w >> 7]++;
    }
    int cur[NTB]; int run = 0;
    #pragma unroll
    for (int i = 0; i < NTB; ++i) { cur[i] = run; run += c[i]; }
    unsigned short* my = srow + t*PSROW;
    #pragma unroll 5
    for (int q4 = 0; q4 < SS/4; ++q4) {
        int4 v = ir[q4];
        my[cur[v.x >> 7]++] = (unsigned short)v.x;
        my[cur[v.y >> 7]++] = (unsigned short)v.y;
        my[cur[v.z >> 7]++] = (unsigned short)v.z;
        my[cur[v.w >> 7]++] = (unsigned short)v.w;
    }
    __syncthreads();

    // coalesced copy out: dst u32-contiguous, src stride 41 words (no conflicts)
    const unsigned* s32 = (const unsigned*)srow;
    unsigned* d32 = (unsigned*)(g_sidx + (size_t)l0*SS);
    #pragma unroll 8
    for (int w = t; w < PSL*(SS/2); w += PSL) {
        int row = w / (SS/2), k = w % (SS/2);
        d32[w] = s32[row*(PSROW/2) + k];
    }
}

// ---------------------------------------------------------------------------
// Kernel 1: sampled scores -> M[b,h,l] + V column sums. R5-validated gather
// shape (warp per (b,h,l); 4 independent 256B LDG gathers per warp-iter),
// indices PRESORTED by key tile so co-resident same-bh CTAs walk tiles in
// the same order (R14 measured 82.8% L1 on this ordering). ~2KB smem and no
// smem atomics -> the L1TEX pipe carries only the gather.
// ---------------------------------------------------------------------------
__global__ void k_sample(const float* __restrict__ Q, const float* __restrict__ K,
                         const float* __restrict__ V) {
    __shared__ float sv[8][64];

    int t = threadIdx.x, lane = t & 31, warp = t >> 5;
    int gw = blockIdx.x * 8 + warp;
    int l  = gw & (LL-1);
    int bh = gw >> 11;
    int b = bh >> 3, h = bh & 7;
    int grp = lane >> 3, lg = lane & 7;

    const float* qrow = Q + (((size_t)b*LL + l)*HH + h)*DD;
    float4 q0 = *(const float4*)(qrow + lg*8);
    float4 q1 = *(const float4*)(qrow + lg*8 + 4);

    // V row for this l (coalesced float2 per lane)
    float2 vv = *(const float2*)(V + (((size_t)b*LL + l)*HH + h)*DD + lane*2);
    sv[warp][lane*2] = vv.x; sv[warp][lane*2+1] = vv.y;

    const unsigned short* irow = g_sidx + (size_t)l*SS;
    float vmax = -CUDART_INF_F, vsum = 0.f;

    #pragma unroll 5
    for (int it = 0; it < SS/4; ++it) {
        int j = irow[it*4 + grp];
        const float* krow = K + (((size_t)b*LL + j)*HH + h)*DD + lg*8;
        float4 k0 = *(const float4*)(krow);
        float4 k1 = *(const float4*)(krow + 4);
        float p = q0.x*k0.x + q0.y*k0.y + q0.z*k0.z + q0.w*k0.w
                + q1.x*k1.x + q1.y*k1.y + q1.z*k1.z + q1.w*k1.w;
        p += __shfl_xor_sync(0xffffffffu, p, 4);
        p += __shfl_xor_sync(0xffffffffu, p, 2);
        p += __shfl_xor_sync(0xffffffffu, p, 1);
        vmax = fmaxf(vmax, p);
        vsum += p;
    }
    vmax = fmaxf(vmax, __shfl_xor_sync(0xffffffffu, vmax, 8));
    vmax = fmaxf(vmax, __shfl_xor_sync(0xffffffffu, vmax, 16));
    vsum += __shfl_xor_sync(0xffffffffu, vsum, 8);
    vsum += __shfl_xor_sync(0xffffffffu, vsum, 16);
    if (lane == 0) g_M[gw] = vmax - vsum * (1.0f/(float)LL);

    __syncthreads();
    if (t < 64) {
        float s = sv[0][t] + sv[1][t] + sv[2][t] + sv[3][t]
                + sv[4][t] + sv[5][t] + sv[6][t] + sv[7][t];
        atomicAdd(&g_vmean[bh*64 + t], s);
    }
}

// ---------------------------------------------------------------------------
// Kernel 2: per-(b,h) top-80 (radix select + bitonic, exact jax.lax.top_k
// semantics), winner replay, V_mean broadcast fill. (R13/R14-validated body.)
// ---------------------------------------------------------------------------
__global__ void k_topk(float* __restrict__ out) {
    int bh = blockIdx.x, t = threadIdx.x, lane = t & 31;
    int b = bh >> 3, h = bh & 7;
    __shared__ unsigned su[LL];
    __shared__ int hist[256];
    __shared__ int scnt[2];
    __shared__ unsigned long long keys[128];
    __shared__ int eqbuf[256];
    __shared__ int cgt, ceq;
    __shared__ int stop[UU];
    __shared__ int win[UU];
    __shared__ float mean[64];

    if (t < 64) {
        mean[t] = g_vmean[bh*64 + t] * (1.0f/(float)LL);
        g_vmean[bh*64 + t] = 0.f;           // reset for next graph replay
    }
    for (int i = t; i < LL; i += 256) {
        unsigned bb = __float_as_uint(g_M[bh*LL + i]);
        su[i] = (bb & 0x80000000u) ? ~bb : (bb | 0x80000000u);
    }
    __syncthreads();

    // broadcast-fill all 80 output rows with V_mean (winners overwritten later)
    for (int e = t; e < UU*64; e += 256) {
        int j = e >> 6, d = e & 63;
        out[(((size_t)b*UU + j)*HH + h)*DD + d] = mean[d];
    }

    // 4-pass byte radix: T = 80th-largest transformed value
    unsigned prefix = 0, prefmask = 0;
    int need = UU;
    for (int pass = 0; pass < 4; ++pass) {
        int shift = 24 - pass*8;
        hist[t] = 0;
        __syncthreads();
        for (int i = t; i < LL; i += 256) {
            unsigned u = su[i];
            if ((u & prefmask) == prefix) atomicAdd(&hist[(u >> shift) & 0xFF], 1);
        }
        __syncthreads();
        if (t < 32) {
            int base = 255 - t*8;
            int s = 0;
            #pragma unroll
            for (int e = 0; e < 8; ++e) s += hist[base - e];
            int pre = s;
            #pragma unroll
            for (int o = 1; o < 32; o <<= 1) {
                int v = __shfl_up_sync(0xffffffffu, pre, o);
                if (lane >= o) pre += v;
            }
            int excl = pre - s;
            if (excl < need && need <= pre) {
                int acc = excl;
                #pragma unroll
                for (int e = 0; e < 8; ++e) {
                    int hb = hist[base - e];
                    if (acc + hb >= need) { scnt[0] = base - e; scnt[1] = acc; break; }
                    acc += hb;
                }
            }
        }
        __syncthreads();
        prefix |= ((unsigned)scnt[0]) << shift;
        prefmask |= 0xFFu << shift;
        need -= scnt[1];
        __syncthreads();
    }
    unsigned T = prefix;

    if (t == 0) { cgt = 0; ceq = 0; }
    __syncthreads();
    for (int i = t; i < LL; i += 256) {
        unsigned u = su[i];
        if (u > T) {
            int p = atomicAdd(&cgt, 1);
            keys[p] = ((unsigned long long)u << 32) | (unsigned)(~i);
        } else if (u == T) {
            int p = atomicAdd(&ceq, 1);
            if (p < 256) eqbuf[p] = i;
        }
    }
    __syncthreads();
    if (t == 0) {
        int base = cgt;
        int ce = min(ceq, 256);
        for (int k = 0; k < need; ++k) {
            int mi = 0x7fffffff, mp = -1;
            for (int e = 0; e < ce; ++e)
                if (eqbuf[e] < mi) { mi = eqbuf[e]; mp = e; }
            keys[base + k] = ((unsigned long long)T << 32) | (unsigned)(~mi);
            eqbuf[mp] = 0x7fffffff;
        }
    }
    for (int i = t; i < 128; i += 256) if (i >= UU) keys[i] = 0ULL;
    __syncthreads();

    // bitonic sort, 128 elements, descending (=> value desc, index asc)
    for (int ksz = 2; ksz <= 128; ksz <<= 1) {
        for (int jst = ksz >> 1; jst > 0; jst >>= 1) {
            __syncthreads();
            if (t < 128) {
                int ixj = t ^ jst;
                if (ixj > t) {
                    unsigned long long a = keys[t], c = keys[ixj];
                    bool up = (t & ksz) == 0;
                    if (up ? (a < c) : (a > c)) { keys[t] = c; keys[ixj] = a; }
                }
            }
        }
    }
    __syncthreads();

    if (t < UU) {
        stop[t] = (int)(~(unsigned)(keys[t] & 0xffffffffu));
        win[t] = -1;
    }
    __syncthreads();
    if (t == 0) {
        for (int u = 0; u < UU; ++u) { int jj = min(stop[u], UU-1); win[jj] = u; }
        int n = 0;
        for (int jj = 0; jj < UU; ++jj) {
            if (win[jj] >= 0) {
                g_wl[bh*UU + n] = stop[win[jj]];
                g_wj[bh*UU + n] = jj;
                n++;
            }
        }
        g_nw[bh] = n;
    }
}

// ---------------------------------------------------------------------------
// Kernel 3: split-K attention partials for winner rows with last-split-block
// combine. SPLIT=16, CHUNK=128, 256 threads, grid (bh, UST=8, SPLIT).
// (Measured 18.8-19.5us across R6-R14 — verbatim, incl. the UST=8 grid.)
// ---------------------------------------------------------------------------
__global__ void k_attn(const float* __restrict__ Q, const float* __restrict__ K,
                       const float* __restrict__ V, float* __restrict__ out) {
    int bh = blockIdx.x;
    int n = g_nw[bh];
    int b = bh >> 3, h = bh & 7;
    int sp = blockIdx.z, k0 = sp * CHUNK;

    __shared__ float q[DD];
    __shared__ float p[CHUNK];
    __shared__ float red[8];
    __shared__ float ac[4][64];
    __shared__ int lastf;
    int t = threadIdx.x, lane = t & 31, warp = t >> 5;
    int grp = lane >> 3, lg = lane & 7;

    for (int u = blockIdx.y; u < n; u += UST) {
        int l = g_wl[bh*UU + u];
        if (t < DD) q[t] = Q[(((size_t)b*LL + l)*HH + h)*DD + t];
        __syncthreads();
        float4 q0 = ((float4*)q)[lg*2];
        float4 q1 = ((float4*)q)[lg*2 + 1];

        float lmax = -CUDART_INF_F;
        #pragma unroll
        for (int it = 0; it < 4; ++it) {
            int kk = warp*16 + it*4 + grp;
            const float* kr = K + (((size_t)b*LL + k0 + kk)*HH + h)*DD + lg*8;
            float4 k0v = *(const float4*)kr;
            float4 k1v = *(const float4*)(kr + 4);
            float s = q0.x*k0v.x + q0.y*k0v.y + q0.z*k0v.z + q0.w*k0v.w
                    + q1.x*k1v.x + q1.y*k1v.y + q1.z*k1v.z + q1.w*k1v.w;
            s += __shfl_xor_sync(0xffffffffu, s, 4);
            s += __shfl_xor_sync(0xffffffffu, s, 2);
            s += __shfl_xor_sync(0xffffffffu, s, 1);
            s *= 0.125f;                 // 1/sqrt(64)
            if (lg == 0) p[kk] = s;
            lmax = fmaxf(lmax, s);
        }
        lmax = fmaxf(lmax, __shfl_xor_sync(0xffffffffu, lmax, 8));
        lmax = fmaxf(lmax, __shfl_xor_sync(0xffffffffu, lmax, 16));
        if (lane == 0) red[warp] = lmax;
        __syncthreads();
        if (t == 0) { float m = red[0]; for (int w = 1; w < 8; ++w) m = fmaxf(m, red[w]); red[0] = m; }
        __syncthreads();
        float m = red[0];
        __syncthreads();

        float e = 0.f;
        if (t < CHUNK) { e = __expf(p[t] - m); p[t] = e; }
        float ls = e;
        #pragma unroll
        for (int o = 16; o; o >>= 1) ls += __shfl_xor_sync(0xffffffffu, ls, o);
        if (lane == 0) red[warp] = ls;
        __syncthreads();
        float ssumv = red[0]+red[1]+red[2]+red[3]+red[4]+red[5]+red[6]+red[7];

        int g4 = t >> 6, d = t & 63;
        float acc = 0.f;
        #pragma unroll 8
        for (int kk = g4; kk < CHUNK; kk += 4)
            acc += p[kk] * V[(((size_t)b*LL + k0 + kk)*HH + h)*DD + d];
        ac[g4][d] = acc;
        __syncthreads();
        int base = (bh*UU + u)*SPLIT + sp;
        if (t < 64)
            g_pv[(size_t)base*DD + t] = ac[0][t] + ac[1][t] + ac[2][t] + ac[3][t];
        if (t == 0) { g_pmax[base] = m; g_psum[base] = ssumv; }

        __threadfence();
        __syncthreads();
        if (t == 0) {
            int old = atomicAdd(&g_cu[bh*UU + u], 1);
            lastf = (old == SPLIT - 1);
        }
        __syncthreads();
        if (lastf) {
            if (t == 0) g_cu[bh*UU + u] = 0;   // self-reset for replay
            if (t < 64) {
                int cb = (bh*UU + u)*SPLIT;
                float mm = -CUDART_INF_F;
                #pragma unroll
                for (int i = 0; i < SPLIT; ++i) mm = fmaxf(mm, g_pmax[cb + i]);
                float s = 0.f, pv = 0.f;
                #pragma unroll
                for (int i = 0; i < SPLIT; ++i) {
                    float w = __expf(g_pmax[cb + i] - mm);
                    s  += g_psum[cb + i] * w;
                    pv += g_pv[(size_t)(cb + i)*DD + t] * w;
                }
                int j = g_wj[bh*UU + u];
                out[(((size_t)b*UU + j)*HH + h)*DD + t] = pv / s;
            }
        }
        __syncthreads();
    }
}

// ---------------------------------------------------------------------------
extern "C" void kernel_launch(void* const* d_in, const int* in_sizes, int n_in,
                              void* d_out, int out_size) {
    const float* Q   = (const float*)d_in[0];
    const float* K   = (const float*)d_in[1];
    const float* V   = (const float*)d_in[2];
    const int*   idx = (const int*)d_in[3];
    float* out = (float*)d_out;

    k_presort<<<LL/PSL, PSL>>>(idx);
    k_sample<<<(BB*HH*LL)/8, 256>>>(Q, K, V);
    k_topk<<<BHN, 256>>>(out);
    dim3 ga(BHN, UST, SPLIT);
    k_attn<<<ga, 256>>>(Q, K, V, out);
}

// round 17
// speedup vs baseline: 1.6836x; 1.5718x over previous
#include <cuda_runtime.h>
#include <cuda_bf16.h>
#include <math_constants.h>

// Problem constants (fixed by the benchmark)
#define BB 2
#define LL 2048
#define HH 8
#define DD 64
#define UU 80
#define SS 80
#define BHN (BB*HH)
#define SPLIT 16
#define CHUNK (LL/SPLIT)      // 128 keys per split block
#define UST 8                 // u-stride for winner loop
#define NTB 16                // sort buckets (j>>7 -> 32KB key tiles)

// Scratch (device globals; zero-initialized at module load)
__device__ float g_M[BB*HH*LL];           // sparsity measure M[b,h,l]
__device__ float g_vmean[BHN*DD];         // V column sums (atomic; reset by k_topk)
__device__ int   g_cu[BHN*UU];            // per-(bh,u) split counter (self-reset)
__device__ int   g_nw[BHN];               // winners per (b,h)
__device__ int   g_wl[BHN*UU];            // winner: source token l
__device__ int   g_wj[BHN*UU];            // winner: output slot j
__device__ float g_pmax[BHN*UU*SPLIT];    // split-softmax partial max
__device__ float g_psum[BHN*UU*SPLIT];    // split-softmax partial sum(exp)
__device__ float g_pv  [BHN*UU*SPLIT*DD]; // split partial (unnormalized) PV

// ---------------------------------------------------------------------------
// Kernel 1: sampled scores -> M[b,h,l] + V column sums (R14 structure).
// Warp-local TILE SORT of the 80 sample indices now uses ballots + popc on
// the ALU pipe (L1TEX is the measured bottleneck at 82.8%; ALU is at ~12%).
// Deterministic round-major order within buckets; gather loop identical to
// the validated R5/R14 shape (4 independent 256B LDG gathers per warp-iter,
// tile-sorted order -> 82.8% L1 hit measured in R14).
// ---------------------------------------------------------------------------
__global__ void k_sample(const float* __restrict__ Q, const float* __restrict__ K,
                         const float* __restrict__ V, const int* __restrict__ idx) {
    __shared__ float sv[8][64];
    __shared__ unsigned short sjb[8][SS];   // per-warp tile-sorted sample indices

    int t = threadIdx.x, lane = t & 31, warp = t >> 5;
    int gw = blockIdx.x * 8 + warp;
    int l  = gw & (LL-1);
    int bh = gw >> 11;
    int b = bh >> 3, h = bh & 7;
    int grp = lane >> 3, lg = lane & 7;

    const float* qrow = Q + (((size_t)b*LL + l)*HH + h)*DD;
    float4 q0 = *(const float4*)(qrow + lg*8);
    float4 q1 = *(const float4*)(qrow + lg*8 + 4);

    // V row for this l (coalesced float2 per lane)
    float2 vv = *(const float2*)(V + (((size_t)b*LL + l)*HH + h)*DD + lane*2);
    sv[warp][lane*2] = vv.x; sv[warp][lane*2+1] = vv.y;

    // ---- ballot-based warp tile-sort (pure ALU; no smem atomics) ----
    const int* irow = idx + l*SS;
    int j0 = irow[lane];
    int j1 = irow[lane + 32];
    int j2 = (lane < 16) ? irow[lane + 64] : 0;
    int b0 = j0 >> 7;
    int b1 = j1 >> 7;
    int b2 = (lane < 16) ? (j2 >> 7) : NTB;   // NTB = never matches
    unsigned ltm = (1u << lane) - 1u;
    int pos0 = 0, pos1 = 0, pos2 = 0;
    int run = 0;
    #pragma unroll
    for (int bb = 0; bb < NTB; ++bb) {
        unsigned e0 = __ballot_sync(0xffffffffu, b0 == bb);
        unsigned e1 = __ballot_sync(0xffffffffu, b1 == bb);
        unsigned e2 = __ballot_sync(0xffffffffu, b2 == bb);
        if (b0 == bb) pos0 = run + __popc(e0 & ltm);
        if (b1 == bb) pos1 = run + __popc(e0) + __popc(e1 & ltm);
        if (b2 == bb) pos2 = run + __popc(e0) + __popc(e1) + __popc(e2 & ltm);
        run += __popc(e0) + __popc(e1) + __popc(e2);
    }
    sjb[warp][pos0] = (unsigned short)j0;
    sjb[warp][pos1] = (unsigned short)j1;
    if (lane < 16) sjb[warp][pos2] = (unsigned short)j2;
    __syncwarp();

    // ---- gather loop (R5/R14-validated shape; indices tile-sorted) ----
    float vmax = -CUDART_INF_F, vsum = 0.f;
    #pragma unroll 5
    for (int it = 0; it < SS/4; ++it) {
        int j = sjb[warp][it*4 + grp];
        const float* krow = K + (((size_t)b*LL + j)*HH + h)*DD + lg*8;
        float4 k0 = *(const float4*)(krow);
        float4 k1 = *(const float4*)(krow + 4);
        float p = q0.x*k0.x + q0.y*k0.y + q0.z*k0.z + q0.w*k0.w
                + q1.x*k1.x + q1.y*k1.y + q1.z*k1.z + q1.w*k1.w;
        p += __shfl_xor_sync(0xffffffffu, p, 4);
        p += __shfl_xor_sync(0xffffffffu, p, 2);
        p += __shfl_xor_sync(0xffffffffu, p, 1);
        vmax = fmaxf(vmax, p);
        vsum += p;
    }
    vmax = fmaxf(vmax, __shfl_xor_sync(0xffffffffu, vmax, 8));
    vmax = fmaxf(vmax, __shfl_xor_sync(0xffffffffu, vmax, 16));
    vsum += __shfl_xor_sync(0xffffffffu, vsum, 8);
    vsum += __shfl_xor_sync(0xffffffffu, vsum, 16);
    if (lane == 0) g_M[gw] = vmax - vsum * (1.0f/(float)LL);

    __syncthreads();
    if (t < 64) {
        float s = sv[0][t] + sv[1][t] + sv[2][t] + sv[3][t]
                + sv[4][t] + sv[5][t] + sv[6][t] + sv[7][t];
        atomicAdd(&g_vmean[bh*64 + t], s);
    }
}

// ---------------------------------------------------------------------------
// Kernel 2: per-(b,h) top-80 (radix select + bitonic, exact jax.lax.top_k
// semantics), winner replay, V_mean broadcast fill. (R13/R14-validated body.)
// ---------------------------------------------------------------------------
__global__ void k_topk(float* __restrict__ out) {
    int bh = blockIdx.x, t = threadIdx.x, lane = t & 31;
    int b = bh >> 3, h = bh & 7;
    __shared__ unsigned su[LL];
    __shared__ int hist[256];
    __shared__ int scnt[2];
    __shared__ unsigned long long keys[128];
    __shared__ int eqbuf[256];
    __shared__ int cgt, ceq;
    __shared__ int stop[UU];
    __shared__ int win[UU];
    __shared__ float mean[64];

    if (t < 64) {
        mean[t] = g_vmean[bh*64 + t] * (1.0f/(float)LL);
        g_vmean[bh*64 + t] = 0.f;           // reset for next graph replay
    }
    for (int i = t; i < LL; i += 256) {
        unsigned bb = __float_as_uint(g_M[bh*LL + i]);
        su[i] = (bb & 0x80000000u) ? ~bb : (bb | 0x80000000u);
    }
    __syncthreads();

    // broadcast-fill all 80 output rows with V_mean (winners overwritten later)
    for (int e = t; e < UU*64; e += 256) {
        int j = e >> 6, d = e & 63;
        out[(((size_t)b*UU + j)*HH + h)*DD + d] = mean[d];
    }

    // 4-pass byte radix: T = 80th-largest transformed value
    unsigned prefix = 0, prefmask = 0;
    int need = UU;
    for (int pass = 0; pass < 4; ++pass) {
        int shift = 24 - pass*8;
        hist[t] = 0;
        __syncthreads();
        for (int i = t; i < LL; i += 256) {
            unsigned u = su[i];
            if ((u & prefmask) == prefix) atomicAdd(&hist[(u >> shift) & 0xFF], 1);
        }
        __syncthreads();
        if (t < 32) {
            int base = 255 - t*8;
            int s = 0;
            #pragma unroll
            for (int e = 0; e < 8; ++e) s += hist[base - e];
            int pre = s;
            #pragma unroll
            for (int o = 1; o < 32; o <<= 1) {
                int v = __shfl_up_sync(0xffffffffu, pre, o);
                if (lane >= o) pre += v;
            }
            int excl = pre - s;
            if (excl < need && need <= pre) {
                int acc = excl;
                #pragma unroll
                for (int e = 0; e < 8; ++e) {
                    int hb = hist[base - e];
                    if (acc + hb >= need) { scnt[0] = base - e; scnt[1] = acc; break; }
                    acc += hb;
                }
            }
        }
        __syncthreads();
        prefix |= ((unsigned)scnt[0]) << shift;
        prefmask |= 0xFFu << shift;
        need -= scnt[1];
        __syncthreads();
    }
    unsigned T = prefix;

    if (t == 0) { cgt = 0; ceq = 0; }
    __syncthreads();
    for (int i = t; i < LL; i += 256) {
        unsigned u = su[i];
        if (u > T) {
            int p = atomicAdd(&cgt, 1);
            keys[p] = ((unsigned long long)u << 32) | (unsigned)(~i);
        } else if (u == T) {
            int p = atomicAdd(&ceq, 1);
            if (p < 256) eqbuf[p] = i;
        }
    }
    __syncthreads();
    if (t == 0) {
        int base = cgt;
        int ce = min(ceq, 256);
        for (int k = 0; k < need; ++k) {
            int mi = 0x7fffffff, mp = -1;
            for (int e = 0; e < ce; ++e)
                if (eqbuf[e] < mi) { mi = eqbuf[e]; mp = e; }
            keys[base + k] = ((unsigned long long)T << 32) | (unsigned)(~mi);
            eqbuf[mp] = 0x7fffffff;
        }
    }
    for (int i = t; i < 128; i += 256) if (i >= UU) keys[i] = 0ULL;
    __syncthreads();

    // bitonic sort, 128 elements, descending (=> value desc, index asc)
    for (int ksz = 2; ksz <= 128; ksz <<= 1) {
        for (int jst = ksz >> 1; jst > 0; jst >>= 1) {
            __syncthreads();
            if (t < 128) {
                int ixj = t ^ jst;
                if (ixj > t) {
                    unsigned long long a = keys[t], c = keys[ixj];
                    bool up = (t & ksz) == 0;
                    if (up ? (a < c) : (a > c)) { keys[t] = c; keys[ixj] = a; }
                }
            }
        }
    }
    __syncthreads();

    if (t < UU) {
        stop[t] = (int)(~(unsigned)(keys[t] & 0xffffffffu));
        win[t] = -1;
    }
    __syncthreads();
    if (t == 0) {
        for (int u = 0; u < UU; ++u) { int jj = min(stop[u], UU-1); win[jj] = u; }
        int n = 0;
        for (int jj = 0; jj < UU; ++jj) {
            if (win[jj] >= 0) {
                g_wl[bh*UU + n] = stop[win[jj]];
                g_wj[bh*UU + n] = jj;
                n++;
            }
        }
        g_nw[bh] = n;
    }
}

// ---------------------------------------------------------------------------
// Kernel 3: split-K attention partials for winner rows with last-split-block
// combine. SPLIT=16, CHUNK=128, 256 threads, grid (bh, UST=8, SPLIT).
// (Measured 18.7-19.5us across R6-R16 — verbatim.)
// ---------------------------------------------------------------------------
__global__ void k_attn(const float* __restrict__ Q, const float* __restrict__ K,
                       const float* __restrict__ V, float* __restrict__ out) {
    int bh = blockIdx.x;
    int n = g_nw[bh];
    int b = bh >> 3, h = bh & 7;
    int sp = blockIdx.z, k0 = sp * CHUNK;

    __shared__ float q[DD];
    __shared__ float p[CHUNK];
    __shared__ float red[8];
    __shared__ float ac[4][64];
    __shared__ int lastf;
    int t = threadIdx.x, lane = t & 31, warp = t >> 5;
    int grp = lane >> 3, lg = lane & 7;

    for (int u = blockIdx.y; u < n; u += UST) {
        int l = g_wl[bh*UU + u];
        if (t < DD) q[t] = Q[(((size_t)b*LL + l)*HH + h)*DD + t];
        __syncthreads();
        float4 q0 = ((float4*)q)[lg*2];
        float4 q1 = ((float4*)q)[lg*2 + 1];

        float lmax = -CUDART_INF_F;
        #pragma unroll
        for (int it = 0; it < 4; ++it) {
            int kk = warp*16 + it*4 + grp;
            const float* kr = K + (((size_t)b*LL + k0 + kk)*HH + h)*DD + lg*8;
            float4 k0v = *(const float4*)kr;
            float4 k1v = *(const float4*)(kr + 4);
            float s = q0.x*k0v.x + q0.y*k0v.y + q0.z*k0v.z + q0.w*k0v.w
                    + q1.x*k1v.x + q1.y*k1v.y + q1.z*k1v.z + q1.w*k1v.w;
            s += __shfl_xor_sync(0xffffffffu, s, 4);
            s += __shfl_xor_sync(0xffffffffu, s, 2);
            s += __shfl_xor_sync(0xffffffffu, s, 1);
            s *= 0.125f;                 // 1/sqrt(64)
            if (lg == 0) p[kk] = s;
            lmax = fmaxf(lmax, s);
        }
        lmax = fmaxf(lmax, __shfl_xor_sync(0xffffffffu, lmax, 8));
        lmax = fmaxf(lmax, __shfl_xor_sync(0xffffffffu, lmax, 16));
        if (lane == 0) red[warp] = lmax;
        __syncthreads();
        if (t == 0) { float m = red[0]; for (int w = 1; w < 8; ++w) m = fmaxf(m, red[w]); red[0] = m; }
        __syncthreads();
        float m = red[0];
        __syncthreads();

        float e = 0.f;
        if (t < CHUNK) { e = __expf(p[t] - m); p[t] = e; }
        float ls = e;
        #pragma unroll
        for (int o = 16; o; o >>= 1) ls += __shfl_xor_sync(0xffffffffu, ls, o);
        if (lane == 0) red[warp] = ls;
        __syncthreads();
        float ssumv = red[0]+red[1]+red[2]+red[3]+red[4]+red[5]+red[6]+red[7];

        int g4 = t >> 6, d = t & 63;
        float acc = 0.f;
        #pragma unroll 8
        for (int kk = g4; kk < CHUNK; kk += 4)
            acc += p[kk] * V[(((size_t)b*LL + k0 + kk)*HH + h)*DD + d];
        ac[g4][d] = acc;
        __syncthreads();
        int base = (bh*UU + u)*SPLIT + sp;
        if (t < 64)
            g_pv[(size_t)base*DD + t] = ac[0][t] + ac[1][t] + ac[2][t] + ac[3][t];
        if (t == 0) { g_pmax[base] = m; g_psum[base] = ssumv; }

        __threadfence();
        __syncthreads();
        if (t == 0) {
            int old = atomicAdd(&g_cu[bh*UU + u], 1);
            lastf = (old == SPLIT - 1);
        }
        __syncthreads();
        if (lastf) {
            if (t == 0) g_cu[bh*UU + u] = 0;   // self-reset for replay
            if (t < 64) {
                int cb = (bh*UU + u)*SPLIT;
                float mm = -CUDART_INF_F;
                #pragma unroll
                for (int i = 0; i < SPLIT; ++i) mm = fmaxf(mm, g_pmax[cb + i]);
                float s = 0.f, pv = 0.f;
                #pragma unroll
                for (int i = 0; i < SPLIT; ++i) {
                    float w = __expf(g_pmax[cb + i] - mm);
                    s  += g_psum[cb + i] * w;
                    pv += g_pv[(size_t)(cb + i)*DD + t] * w;
                }
                int j = g_wj[bh*UU + u];
                out[(((size_t)b*UU + j)*HH + h)*DD + t] = pv / s;
            }
        }
        __syncthreads();
    }
}

// ---------------------------------------------------------------------------
extern "C" void kernel_launch(void* const* d_in, const int* in_sizes, int n_in,
                              void* d_out, int out_size) {
    const float* Q   = (const float*)d_in[0];
    const float* K   = (const float*)d_in[1];
    const float* V   = (const float*)d_in[2];
    const int*   idx = (const int*)d_in[3];
    float* out = (float*)d_out;

    k_sample<<<(BB*HH*LL)/8, 256>>>(Q, K, V, idx);
    k_topk<<<BHN, 256>>>(out);
    dim3 ga(BHN, UST, SPLIT);
    k_attn<<<ga, 256>>>(Q, K, V, out);
}